// round 4
// baseline (speedup 1.0000x reference)
#include <cuda_runtime.h>

#define BB 4
#define CC 17
#define TT 75000
#define HH 32
#define NTHREADS 256
#define TILE 4096
#define NTILE 19          // ceil(75000/4096)
#define MAXPART 256

// Deterministic partial accumulation scratch: [combo 28][b 4][h 32][part 256][16]
__device__ float g_partial[28][4][32][MAXPART][16];

// skewed shared index: kills bank conflicts for strided chains
#define SK(i) ((i) + ((i) >> 5))

typedef unsigned long long ull;

// ---------------- f32x2 helpers ----------------
__device__ __forceinline__ ull pack2(float a, float b) {
    ull r; asm("mov.b64 %0, {%1, %2};" : "=l"(r) : "f"(a), "f"(b)); return r;
}
__device__ __forceinline__ ull dup2(float a) {
    ull r; asm("mov.b64 %0, {%1, %1};" : "=l"(r) : "f"(a)); return r;
}
__device__ __forceinline__ void mul2(ull& z, ull a, ull b) {
    asm("mul.rn.f32x2 %0, %1, %2;" : "=l"(z) : "l"(a), "l"(b));
}
__device__ __forceinline__ void fma2(ull& z, ull a, ull b) {
    asm("fma.rn.f32x2 %0, %1, %2, %0;" : "+l"(z) : "l"(a), "l"(b));
}
__device__ __forceinline__ void unpack2(ull z, float& lo, float& hi) {
    asm("mov.b64 {%0, %1}, %2;" : "=f"(lo), "=f"(hi) : "l"(z));
}

// ---------------- per-position conv + bucket reduce ----------------
// gd: 9-slot rotating window of duplicated g values ({g,g}); rot known at compile
// time after unroll. w2[kk][j] = { w[2kk][j], w[2kk+1][j] }.
__device__ __forceinline__ void conv_step(const ull gd[9], int rot,
                                          const ull w2[4][9],
                                          float am[8], float an[8], float validf) {
    ull acc[4];
    {
        ull g2 = gd[rot % 9];
#pragma unroll
        for (int kk = 0; kk < 4; kk++) mul2(acc[kk], g2, w2[kk][0]);
    }
#pragma unroll
    for (int j = 1; j < 9; j++) {
        ull g2 = gd[(rot + j) % 9];
#pragma unroll
        for (int kk = 0; kk < 4; kk++) fma2(acc[kk], g2, w2[kk][j]);
    }
    float z[8];
#pragma unroll
    for (int kk = 0; kk < 4; kk++) unpack2(acc[kk], z[2 * kk], z[2 * kk + 1]);

    float mx = fmaxf(fmaxf(fmaxf(z[0], z[1]), fmaxf(z[2], z[3])),
                     fmaxf(fmaxf(z[4], z[5]), fmaxf(z[6], z[7])));
    float mn = fminf(fminf(fminf(z[0], z[1]), fminf(z[2], z[3])),
                     fminf(fminf(z[4], z[5]), fminf(z[6], z[7])));
    float mxv = mx * validf;
#pragma unroll
    for (int k = 0; k < 8; k++) {
        am[k] += (z[k] == mx) ? mxv : 0.f;
        an[k] += (z[k] == mn) ? validf : 0.f;
    }
}

__device__ __forceinline__ void load_w2(const float* __restrict__ W, int ci, int h,
                                        ull w2[4][9]) {
    const float* wp = W + (ci * 256 + h * 8) * 9;
#pragma unroll
    for (int kk = 0; kk < 4; kk++)
#pragma unroll
        for (int j = 0; j < 9; j++)
            w2[kk][j] = pack2(__ldg(wp + (2 * kk) * 9 + j), __ldg(wp + (2 * kk + 1) * 9 + j));
}

// block-wide (one h per block) partial write, via shfl + shared
__device__ __forceinline__ void block_write_partial(float* sw, float am[8], float an[8],
                                                    int ci, int b, int h, int blk) {
    int tid = threadIdx.x;
    int lane = tid & 31, warp = tid >> 5;
#pragma unroll
    for (int o = 0; o < 16; o++) {
        float v = (o < 8) ? am[o] : an[o - 8];
        v += __shfl_down_sync(0xffffffffu, v, 16);
        v += __shfl_down_sync(0xffffffffu, v, 8);
        v += __shfl_down_sync(0xffffffffu, v, 4);
        v += __shfl_down_sync(0xffffffffu, v, 2);
        v += __shfl_down_sync(0xffffffffu, v, 1);
        if (lane == 0) sw[warp * 16 + o] = v;
    }
    __syncthreads();
    if (tid < 16) {
        float s = 0.f;
#pragma unroll
        for (int wN = 0; wN < 8; wN++) s += sw[wN * 16 + tid];
        g_partial[ci][b][h][blk][tid] = s;
    }
}

// per-warp (one h per warp) partial write, shfl only
__device__ __forceinline__ void warp_write_partial(float am[8], float an[8],
                                                   int ci, int b, int h, int part) {
    int lane = threadIdx.x & 31;
#pragma unroll
    for (int o = 0; o < 16; o++) {
        float v = (o < 8) ? am[o] : an[o - 8];
        v += __shfl_down_sync(0xffffffffu, v, 16);
        v += __shfl_down_sync(0xffffffffu, v, 8);
        v += __shfl_down_sync(0xffffffffu, v, 4);
        v += __shfl_down_sync(0xffffffffu, v, 2);
        v += __shfl_down_sync(0xffffffffu, v, 1);
        if (lane == 0) g_partial[ci][b][h][part][o] = v;
    }
}

// ============================================================================
// Path A: small dilation (di 0..8). Shared g tile (skewed), register sliding
// window along chains of stride D: 16 positions/thread, 1 LDS per slide.
// ============================================================================
template <int DI, int DIFF>
__device__ __forceinline__ void tile_body(int rlin, float* g_sh,
                                          const float* __restrict__ X,
                                          const float* __restrict__ W,
                                          const int* __restrict__ idx) {
    constexpr int D = 1 << DI;
    constexpr int HALO = 4 * D;
    constexpr int N = TILE + 2 * HALO;
    constexpr int CI = DI * 2 + DIFF;
    constexpr int Te = TT - DIFF;

    int tile = rlin % NTILE;
    int h = (rlin / NTILE) % HH;
    int b = rlin / (NTILE * HH);
    int t0 = tile * TILE;
    int tid = threadIdx.x;

    int off[8];
    {
        const int* ip = idx + (CI * HH + h) * 8;
#pragma unroll
        for (int i = 0; i < 8; i++) off[i] = ip[i] * TT;
    }
    const float* Xb = X + b * CC * TT;

    // ---- build g tile (zero padded outside [0, Te)), skewed layout ----
    if (DIFF == 0) {
        for (int i = 2 * tid; i < N; i += 2 * NTHREADS) {
            int t = t0 - HALO + i;
            float v0 = 0.f, v1 = 0.f;
            if (t >= 0 && t + 1 < TT) {
#pragma unroll
                for (int c = 0; c < 8; c++) {
                    float2 x = __ldg((const float2*)(Xb + off[c] + t));
                    v0 += x.x; v1 += x.y;
                }
            } else {
                if (t >= 0 && t < TT) {
#pragma unroll
                    for (int c = 0; c < 8; c++) v0 += __ldg(Xb + off[c] + t);
                }
                if (t + 1 >= 0 && t + 1 < TT) {
#pragma unroll
                    for (int c = 0; c < 8; c++) v1 += __ldg(Xb + off[c] + t + 1);
                }
            }
            g_sh[SK(i)] = v0;
            g_sh[SK(i + 1)] = v1;
        }
    } else {
        for (int i = 2 * tid; i < N; i += 2 * NTHREADS) {
            int t = t0 - HALO + i;
            float s0 = 0.f, s1 = 0.f, s2 = 0.f;
            if (t >= 0 && t + 2 < TT) {
#pragma unroll
                for (int c = 0; c < 8; c++) {
                    float2 x = __ldg((const float2*)(Xb + off[c] + t));
                    s0 += x.x; s1 += x.y;
                    s2 += __ldg(Xb + off[c] + t + 2);
                }
            } else {
                if (t >= 0 && t < TT) {
#pragma unroll
                    for (int c = 0; c < 8; c++) s0 += __ldg(Xb + off[c] + t);
                }
                if (t + 1 >= 0 && t + 1 < TT) {
#pragma unroll
                    for (int c = 0; c < 8; c++) s1 += __ldg(Xb + off[c] + t + 1);
                }
                if (t + 2 >= 0 && t + 2 < TT) {
#pragma unroll
                    for (int c = 0; c < 8; c++) s2 += __ldg(Xb + off[c] + t + 2);
                }
            }
            g_sh[SK(i)] = (t >= 0 && t < Te) ? (s1 - s0) : 0.f;
            g_sh[SK(i + 1)] = (t + 1 >= 0 && t + 1 < Te) ? (s2 - s1) : 0.f;
        }
    }

    ull w2[4][9];
    load_w2(W, CI, h, w2);
    __syncthreads();

    // chain assignment: c = tid % D, s = tid / D, 16 positions stride D
    int c = tid % D;
    int s = tid / D;
    int q0 = c + s * (16 * D);

    ull gd[9];
#pragma unroll
    for (int j = 0; j < 9; j++) gd[j] = dup2(g_sh[SK(q0 + j * D)]);

    float am[8] = {0, 0, 0, 0, 0, 0, 0, 0};
    float an[8] = {0, 0, 0, 0, 0, 0, 0, 0};
    int tb = t0 + q0;

#pragma unroll
    for (int m = 0; m < 16; m++) {
        float validf = (tb + m * D < Te) ? 1.0f : 0.0f;
        conv_step(gd, m % 9, w2, am, an, validf);
        if (m < 15) gd[m % 9] = dup2(g_sh[SK(q0 + (m + 9) * D)]);
    }
    __syncthreads();
    block_write_partial(g_sh, am, an, CI, b, h, tile);
}

__global__ void __launch_bounds__(256, 2)
tile_all(const float* __restrict__ X, const float* __restrict__ W,
         const int* __restrict__ idx) {
    __shared__ float g_sh[6336];   // max N=6144 skewed: 6144 + 192
    int ci = blockIdx.x / (NTILE * HH * BB);
    int r = blockIdx.x % (NTILE * HH * BB);
    switch (ci) {
        case 0:  tile_body<0, 0>(r, g_sh, X, W, idx); break;
        case 1:  tile_body<0, 1>(r, g_sh, X, W, idx); break;
        case 2:  tile_body<1, 0>(r, g_sh, X, W, idx); break;
        case 3:  tile_body<1, 1>(r, g_sh, X, W, idx); break;
        case 4:  tile_body<2, 0>(r, g_sh, X, W, idx); break;
        case 5:  tile_body<2, 1>(r, g_sh, X, W, idx); break;
        case 6:  tile_body<3, 0>(r, g_sh, X, W, idx); break;
        case 7:  tile_body<3, 1>(r, g_sh, X, W, idx); break;
        case 8:  tile_body<4, 0>(r, g_sh, X, W, idx); break;
        case 9:  tile_body<4, 1>(r, g_sh, X, W, idx); break;
        case 10: tile_body<5, 0>(r, g_sh, X, W, idx); break;
        case 11: tile_body<5, 1>(r, g_sh, X, W, idx); break;
        case 12: tile_body<6, 0>(r, g_sh, X, W, idx); break;
        case 13: tile_body<6, 1>(r, g_sh, X, W, idx); break;
        case 14: tile_body<7, 0>(r, g_sh, X, W, idx); break;
        case 15: tile_body<7, 1>(r, g_sh, X, W, idx); break;
        case 16: tile_body<8, 0>(r, g_sh, X, W, idx); break;
        case 17: tile_body<8, 1>(r, g_sh, X, W, idx); break;
    }
}

// ============================================================================
// Path B: large dilation (di 9..13). Residue walk; 8 warps = 8 h per block
// share X lines in L1. Per-warp partials.
// ============================================================================
template <int DIFF>
__device__ __forceinline__ float gsumT(const float* __restrict__ Xb,
                                       const int off[8], int t) {
    float s = 0.f;
#pragma unroll
    for (int i = 0; i < 8; i++) {
        const float* p = Xb + off[i] + t;
        float x = __ldg(p);
        if (DIFF) x = __ldg(p + 1) - x;
        s += x;
    }
    return s;
}

template <int DI, int DIFF>
__device__ __forceinline__ void residue_body(int rlin,
                                             const float* __restrict__ X,
                                             const float* __restrict__ W,
                                             const int* __restrict__ idx) {
    constexpr int D = 1 << DI;
    constexpr int NRB32 = 1 << (DI - 5);    // residue blocks of 32
    constexpr int CI = 18 + (DI - 9) * 2 + DIFF;
    constexpr int Te = TT - DIFF;

    int rb = rlin % NRB32;
    int hb = (rlin / NRB32) & 3;
    int b = rlin / (NRB32 * 4);
    int lane = threadIdx.x & 31;
    int warp = threadIdx.x >> 5;
    int h = hb * 8 + warp;
    int r = rb * 32 + lane;                 // residue < D
    int M = (Te - r + D - 1) / D;           // strip length >= 1

    int off[8];
    {
        const int* ip = idx + (CI * HH + h) * 8;
#pragma unroll
        for (int i = 0; i < 8; i++) off[i] = ip[i] * TT;
    }
    const float* Xb = X + b * CC * TT;

    ull w2[4][9];
    load_w2(W, CI, h, w2);

    ull gd[9];
#pragma unroll
    for (int j = 0; j < 9; j++) {
        int s = j - 4;
        float v = (s >= 0 && s < M) ? gsumT<DIFF>(Xb, off, r + s * D) : 0.f;
        gd[j] = dup2(v);
    }

    float am[8] = {0, 0, 0, 0, 0, 0, 0, 0};
    float an[8] = {0, 0, 0, 0, 0, 0, 0, 0};

    for (int mb = 0; mb < M; mb += 9) {
#pragma unroll
        for (int u = 0; u < 9; u++) {
            int m = mb + u;
            if (m < M) {
                conv_step(gd, u, w2, am, an, 1.0f);
                int sn = m + 5;
                float v = (sn < M) ? gsumT<DIFF>(Xb, off, r + sn * D) : 0.f;
                gd[u] = dup2(v);
            }
        }
    }
    warp_write_partial(am, an, CI, b, h, rb);
}

__global__ void __launch_bounds__(256, 2)
residue_all(const float* __restrict__ X, const float* __restrict__ W,
            const int* __restrict__ idx) {
    int bx = blockIdx.x;
    int lci, r;
    if      (bx < 256)   { lci = 0; r = bx; }
    else if (bx < 512)   { lci = 1; r = bx - 256; }
    else if (bx < 1024)  { lci = 2; r = bx - 512; }
    else if (bx < 1536)  { lci = 3; r = bx - 1024; }
    else if (bx < 2560)  { lci = 4; r = bx - 1536; }
    else if (bx < 3584)  { lci = 5; r = bx - 2560; }
    else if (bx < 5632)  { lci = 6; r = bx - 3584; }
    else if (bx < 7680)  { lci = 7; r = bx - 5632; }
    else if (bx < 11776) { lci = 8; r = bx - 7680; }
    else                 { lci = 9; r = bx - 11776; }
    switch (lci) {
        case 0: residue_body<9, 0>(r, X, W, idx); break;
        case 1: residue_body<9, 1>(r, X, W, idx); break;
        case 2: residue_body<10, 0>(r, X, W, idx); break;
        case 3: residue_body<10, 1>(r, X, W, idx); break;
        case 4: residue_body<11, 0>(r, X, W, idx); break;
        case 5: residue_body<11, 1>(r, X, W, idx); break;
        case 6: residue_body<12, 0>(r, X, W, idx); break;
        case 7: residue_body<12, 1>(r, X, W, idx); break;
        case 8: residue_body<13, 0>(r, X, W, idx); break;
        case 9: residue_body<13, 1>(r, X, W, idx); break;
    }
}

// ============================================================================
// Deterministic final reduction -> d_out (writes every element)
// ============================================================================
__global__ void reduce_kernel(float* __restrict__ out) {
    int e = blockIdx.x * 256 + threadIdx.x;
    if (e >= BB * 14336) return;
    int b = e / 14336;
    int rem = e % 14336;
    int cig = rem / 512;
    int r2 = rem % 512;
    int which = r2 / 256;
    int hk = r2 % 256;
    int h = hk >> 3, k = hk & 7;
    int np;
    if (cig < 18) np = NTILE;
    else np = 1 << (((cig - 18) >> 1) + 4);   // D/32 parts
    float s = 0.f;
    for (int p = 0; p < np; p++)
        s += g_partial[cig][b][h][p][which * 8 + k];
    out[e] = s;
}

extern "C" void kernel_launch(void* const* d_in, const int* in_sizes, int n_in,
                              void* d_out, int out_size) {
    const float* X = (const float*)d_in[0];
    const float* W = (const float*)d_in[1];
    const int* idx = (const int*)d_in[2];
    float* out = (float*)d_out;

    tile_all<<<18 * NTILE * HH * BB, NTHREADS>>>(X, W, idx);
    residue_all<<<15872, NTHREADS>>>(X, W, idx);
    reduce_kernel<<<(BB * 14336 + 255) / 256, 256>>>(out);
}

// round 7
// speedup vs baseline: 1.0194x; 1.0194x over previous
#include <cuda_runtime.h>

#define BB 4
#define CC 17
#define TT 75000
#define HH 32
#define NTHREADS 256
#define TILE 4096
#define NTILE 19          // ceil(75000/4096)
#define MAXPART 32

// Deterministic partial accumulation scratch: [combo 28][b 4][h 32][part 32][16]
__device__ float g_partial[28][4][32][MAXPART][16];

typedef unsigned long long ull;

// ---------------- f32x2 helpers ----------------
__device__ __forceinline__ ull pack2(float a, float b) {
    ull r; asm("mov.b64 %0, {%1, %2};" : "=l"(r) : "f"(a), "f"(b)); return r;
}
__device__ __forceinline__ ull dup2(float a) {
    ull r; asm("mov.b64 %0, {%1, %1};" : "=l"(r) : "f"(a)); return r;
}
__device__ __forceinline__ void mul2(ull& z, ull a, ull b) {
    asm("mul.rn.f32x2 %0, %1, %2;" : "=l"(z) : "l"(a), "l"(b));
}
__device__ __forceinline__ void fma2(ull& z, ull a, ull b) {
    asm("fma.rn.f32x2 %0, %1, %2, %0;" : "+l"(z) : "l"(a), "l"(b));
}
__device__ __forceinline__ void unpack2(ull z, float& lo, float& hi) {
    asm("mov.b64 {%0, %1}, %2;" : "=f"(lo), "=f"(hi) : "l"(z));
}

// ---------------- per-position conv + bucket reduce ----------------
// gd: 9 slots of pre-duplicated {g,g}; ROT selects rotation (compile-time).
// w2[kk][j] = { w[2kk][j], w[2kk+1][j] }.
template <int ROT>
__device__ __forceinline__ void conv_step(const ull gd[9], const ull w2[4][9],
                                          float am[8], float an[8]) {
    ull acc[4];
    {
        ull g2 = gd[ROT % 9];
#pragma unroll
        for (int kk = 0; kk < 4; kk++) mul2(acc[kk], g2, w2[kk][0]);
    }
#pragma unroll
    for (int j = 1; j < 9; j++) {
        ull g2 = gd[(ROT + j) % 9];
#pragma unroll
        for (int kk = 0; kk < 4; kk++) fma2(acc[kk], g2, w2[kk][j]);
    }
    float z[8];
#pragma unroll
    for (int kk = 0; kk < 4; kk++) unpack2(acc[kk], z[2 * kk], z[2 * kk + 1]);

    float mx = fmaxf(fmaxf(fmaxf(z[0], z[1]), fmaxf(z[2], z[3])),
                     fmaxf(fmaxf(z[4], z[5]), fmaxf(z[6], z[7])));
    float mn = fminf(fminf(fminf(z[0], z[1]), fminf(z[2], z[3])),
                     fminf(fminf(z[4], z[5]), fminf(z[6], z[7])));
#pragma unroll
    for (int k = 0; k < 8; k++) {
        if (z[k] == mx) am[k] += z[k];
        if (z[k] == mn) an[k] += 1.0f;
    }
}

__device__ __forceinline__ void load_w2(const float* __restrict__ W, int ci, int h,
                                        ull w2[4][9]) {
    const float* wp = W + (ci * 256 + h * 8) * 9;
#pragma unroll
    for (int kk = 0; kk < 4; kk++)
#pragma unroll
        for (int j = 0; j < 9; j++)
            w2[kk][j] = pack2(__ldg(wp + (2 * kk) * 9 + j), __ldg(wp + (2 * kk + 1) * 9 + j));
}

__device__ __forceinline__ void block_write_partial(float* sw, float am[8], float an[8],
                                                    int ci, int b, int h, int blk) {
    int tid = threadIdx.x;
    int lane = tid & 31, warp = tid >> 5;
#pragma unroll
    for (int o = 0; o < 16; o++) {
        float v = (o < 8) ? am[o] : an[o - 8];
        v += __shfl_down_sync(0xffffffffu, v, 16);
        v += __shfl_down_sync(0xffffffffu, v, 8);
        v += __shfl_down_sync(0xffffffffu, v, 4);
        v += __shfl_down_sync(0xffffffffu, v, 2);
        v += __shfl_down_sync(0xffffffffu, v, 1);
        if (lane == 0) sw[warp * 16 + o] = v;
    }
    __syncthreads();
    if (tid < 16) {
        float s = 0.f;
#pragma unroll
        for (int wN = 0; wN < 8; wN++) s += sw[wN * 16 + tid];
        g_partial[ci][b][h][blk][tid] = s;
    }
}

// ============================================================================
// Path A: small dilation (di 0..8). Pre-duplicated {g,g} shared tile; each
// thread does 16 positions (stride 256), 9 LDS.64 per position with
// immediate offsets, no dup MOVs.
// ============================================================================
template <int DI, int DIFF>
__device__ __forceinline__ void tile_body(int rlin, ull* g2, float* sw,
                                          const float* __restrict__ X,
                                          const float* __restrict__ W,
                                          const int* __restrict__ idx) {
    constexpr int D = 1 << DI;
    constexpr int HALO = 4 * D;
    constexpr int N = TILE + 2 * HALO;
    constexpr int CI = DI * 2 + DIFF;
    constexpr int Te = TT - DIFF;

    int tile = rlin % NTILE;
    int h = (rlin / NTILE) % HH;
    int b = rlin / (NTILE * HH);
    int t0 = tile * TILE;
    int tid = threadIdx.x;

    int off[8];
    {
        const int* ip = idx + (CI * HH + h) * 8;
#pragma unroll
        for (int i = 0; i < 8; i++) off[i] = ip[i] * TT;
    }
    const float* Xb = X + b * CC * TT;

    // ---- build pre-duplicated g tile (zero padded outside [0, Te)) ----
    if (DIFF == 0) {
        for (int i = 2 * tid; i < N; i += 2 * NTHREADS) {
            int t = t0 - HALO + i;
            float v0 = 0.f, v1 = 0.f;
            if (t >= 0 && t + 1 < TT) {
#pragma unroll
                for (int c = 0; c < 8; c++) {
                    float2 x = __ldg((const float2*)(Xb + off[c] + t));
                    v0 += x.x; v1 += x.y;
                }
            } else {
                if (t >= 0 && t < TT) {
#pragma unroll
                    for (int c = 0; c < 8; c++) v0 += __ldg(Xb + off[c] + t);
                }
                if (t + 1 >= 0 && t + 1 < TT) {
#pragma unroll
                    for (int c = 0; c < 8; c++) v1 += __ldg(Xb + off[c] + t + 1);
                }
            }
            g2[i] = dup2(v0);
            g2[i + 1] = dup2(v1);
        }
    } else {
        for (int i = 2 * tid; i < N; i += 2 * NTHREADS) {
            int t = t0 - HALO + i;
            float s0 = 0.f, s1 = 0.f, s2 = 0.f;
            if (t >= 0 && t + 2 < TT) {
#pragma unroll
                for (int c = 0; c < 8; c++) {
                    float2 x = __ldg((const float2*)(Xb + off[c] + t));
                    s0 += x.x; s1 += x.y;
                    s2 += __ldg(Xb + off[c] + t + 2);
                }
            } else {
                if (t >= 0 && t < TT) {
#pragma unroll
                    for (int c = 0; c < 8; c++) s0 += __ldg(Xb + off[c] + t);
                }
                if (t + 1 >= 0 && t + 1 < TT) {
#pragma unroll
                    for (int c = 0; c < 8; c++) s1 += __ldg(Xb + off[c] + t + 1);
                }
                if (t + 2 >= 0 && t + 2 < TT) {
#pragma unroll
                    for (int c = 0; c < 8; c++) s2 += __ldg(Xb + off[c] + t + 2);
                }
            }
            g2[i] = dup2((t >= 0 && t < Te) ? (s1 - s0) : 0.f);
            g2[i + 1] = dup2((t + 1 >= 0 && t + 1 < Te) ? (s2 - s1) : 0.f);
        }
    }

    ull w2[4][9];
    load_w2(W, CI, h, w2);
    __syncthreads();

    float am[8] = {0, 0, 0, 0, 0, 0, 0, 0};
    float an[8] = {0, 0, 0, 0, 0, 0, 0, 0};

#pragma unroll 1
    for (int p = 0; p < TILE / NTHREADS; p++) {
        int q = tid + p * NTHREADS;
        int t = t0 + q;
        if (t < Te) {
            ull gd[9];
#pragma unroll
            for (int j = 0; j < 9; j++) gd[j] = g2[q + j * D];  // LDS.64, imm offsets
            conv_step<0>(gd, w2, am, an);
        }
    }
    __syncthreads();
    block_write_partial(sw, am, an, CI, b, h, tile);
}

__global__ void __launch_bounds__(256, 2)
tile_all(const float* __restrict__ X, const float* __restrict__ W,
         const int* __restrict__ idx) {
    __shared__ ull g2[TILE + 2 * 4 * 256];   // max N (DI=8): 6144 ull = 48KB
    __shared__ float sw[128];
    int ci = blockIdx.x / (NTILE * HH * BB);
    int r = blockIdx.x % (NTILE * HH * BB);
    switch (ci) {
        case 0:  tile_body<0, 0>(r, g2, sw, X, W, idx); break;
        case 1:  tile_body<0, 1>(r, g2, sw, X, W, idx); break;
        case 2:  tile_body<1, 0>(r, g2, sw, X, W, idx); break;
        case 3:  tile_body<1, 1>(r, g2, sw, X, W, idx); break;
        case 4:  tile_body<2, 0>(r, g2, sw, X, W, idx); break;
        case 5:  tile_body<2, 1>(r, g2, sw, X, W, idx); break;
        case 6:  tile_body<3, 0>(r, g2, sw, X, W, idx); break;
        case 7:  tile_body<3, 1>(r, g2, sw, X, W, idx); break;
        case 8:  tile_body<4, 0>(r, g2, sw, X, W, idx); break;
        case 9:  tile_body<4, 1>(r, g2, sw, X, W, idx); break;
        case 10: tile_body<5, 0>(r, g2, sw, X, W, idx); break;
        case 11: tile_body<5, 1>(r, g2, sw, X, W, idx); break;
        case 12: tile_body<6, 0>(r, g2, sw, X, W, idx); break;
        case 13: tile_body<6, 1>(r, g2, sw, X, W, idx); break;
        case 14: tile_body<7, 0>(r, g2, sw, X, W, idx); break;
        case 15: tile_body<7, 1>(r, g2, sw, X, W, idx); break;
        case 16: tile_body<8, 0>(r, g2, sw, X, W, idx); break;
        case 17: tile_body<8, 1>(r, g2, sw, X, W, idx); break;
    }
}

// ============================================================================
// Path B: large dilation (di 9..13). Residue walk, rotating register window
// (1 dup2 per slide, no shift MOVs), one h per block.
// ============================================================================
template <int DIFF>
__device__ __forceinline__ float gsumT(const float* __restrict__ Xb,
                                       const int off[8], int t) {
    float s = 0.f;
#pragma unroll
    for (int i = 0; i < 8; i++) {
        const float* p = Xb + off[i] + t;
        float x = __ldg(p);
        if (DIFF) x = __ldg(p + 1) - x;
        s += x;
    }
    return s;
}

template <int DI, int DIFF, int U>
__device__ __forceinline__ void residue_step(ull gd[9], const ull w2[4][9],
                                             float am[8], float an[8],
                                             const float* __restrict__ Xb,
                                             const int off[8], int r, int mb, int M) {
    constexpr int D = 1 << DI;
    int m = mb + U;
    if (m < M) {
        conv_step<U>(gd, w2, am, an);
        int sn = m + 5;
        gd[U] = dup2((sn < M) ? gsumT<DIFF>(Xb, off, r + sn * D) : 0.f);
    }
}

template <int DI, int DIFF>
__device__ __forceinline__ void residue_body(int rlin, float* sw,
                                             const float* __restrict__ X,
                                             const float* __restrict__ W,
                                             const int* __restrict__ idx) {
    constexpr int D = 1 << DI;
    constexpr int NRB = 1 << (DI - 8);
    constexpr int CI = 18 + (DI - 9) * 2 + DIFF;
    constexpr int Te = TT - DIFF;

    int rb = rlin % NRB;
    int h = (rlin / NRB) % HH;
    int b = rlin / (NRB * HH);
    int tid = threadIdx.x;
    int r = rb * NTHREADS + tid;            // residue < D
    int M = (Te - r + D - 1) / D;           // strip length >= 1

    int off[8];
    {
        const int* ip = idx + (CI * HH + h) * 8;
#pragma unroll
        for (int i = 0; i < 8; i++) off[i] = ip[i] * TT;
    }
    const float* Xb = X + b * CC * TT;

    ull w2[4][9];
    load_w2(W, CI, h, w2);

    ull gd[9];
#pragma unroll
    for (int j = 0; j < 9; j++) {
        int s = j - 4;
        float v = (s >= 0 && s < M) ? gsumT<DIFF>(Xb, off, r + s * D) : 0.f;
        gd[j] = dup2(v);
    }

    float am[8] = {0, 0, 0, 0, 0, 0, 0, 0};
    float an[8] = {0, 0, 0, 0, 0, 0, 0, 0};

#pragma unroll 1
    for (int mb = 0; mb < M; mb += 9) {
        residue_step<DI, DIFF, 0>(gd, w2, am, an, Xb, off, r, mb, M);
        residue_step<DI, DIFF, 1>(gd, w2, am, an, Xb, off, r, mb, M);
        residue_step<DI, DIFF, 2>(gd, w2, am, an, Xb, off, r, mb, M);
        residue_step<DI, DIFF, 3>(gd, w2, am, an, Xb, off, r, mb, M);
        residue_step<DI, DIFF, 4>(gd, w2, am, an, Xb, off, r, mb, M);
        residue_step<DI, DIFF, 5>(gd, w2, am, an, Xb, off, r, mb, M);
        residue_step<DI, DIFF, 6>(gd, w2, am, an, Xb, off, r, mb, M);
        residue_step<DI, DIFF, 7>(gd, w2, am, an, Xb, off, r, mb, M);
        residue_step<DI, DIFF, 8>(gd, w2, am, an, Xb, off, r, mb, M);
    }
    __syncthreads();
    block_write_partial(sw, am, an, CI, b, h, rb);
}

__global__ void __launch_bounds__(256, 2)
residue_all(const float* __restrict__ X, const float* __restrict__ W,
            const int* __restrict__ idx) {
    __shared__ float sw[128];
    int bx = blockIdx.x;
    int lci, r;
    if      (bx < 256)   { lci = 0; r = bx; }
    else if (bx < 512)   { lci = 1; r = bx - 256; }
    else if (bx < 1024)  { lci = 2; r = bx - 512; }
    else if (bx < 1536)  { lci = 3; r = bx - 1024; }
    else if (bx < 2560)  { lci = 4; r = bx - 1536; }
    else if (bx < 3584)  { lci = 5; r = bx - 2560; }
    else if (bx < 5632)  { lci = 6; r = bx - 3584; }
    else if (bx < 7680)  { lci = 7; r = bx - 5632; }
    else if (bx < 11776) { lci = 8; r = bx - 7680; }
    else                 { lci = 9; r = bx - 11776; }
    switch (lci) {
        case 0: residue_body<9, 0>(r, sw, X, W, idx); break;
        case 1: residue_body<9, 1>(r, sw, X, W, idx); break;
        case 2: residue_body<10, 0>(r, sw, X, W, idx); break;
        case 3: residue_body<10, 1>(r, sw, X, W, idx); break;
        case 4: residue_body<11, 0>(r, sw, X, W, idx); break;
        case 5: residue_body<11, 1>(r, sw, X, W, idx); break;
        case 6: residue_body<12, 0>(r, sw, X, W, idx); break;
        case 7: residue_body<12, 1>(r, sw, X, W, idx); break;
        case 8: residue_body<13, 0>(r, sw, X, W, idx); break;
        case 9: residue_body<13, 1>(r, sw, X, W, idx); break;
    }
}

// ============================================================================
// Deterministic final reduction -> d_out (writes every element)
// ============================================================================
__global__ void reduce_kernel(float* __restrict__ out) {
    int e = blockIdx.x * 256 + threadIdx.x;
    if (e >= BB * 14336) return;
    int b = e / 14336;
    int rem = e % 14336;
    int cig = rem / 512;
    int r2 = rem % 512;
    int which = r2 / 256;
    int hk = r2 % 256;
    int h = hk >> 3, k = hk & 7;
    int np;
    if (cig < 18) np = NTILE;
    else { int di = cig >> 1; np = 1 << (di - 8); }
    float s = 0.f;
    for (int p = 0; p < np; p++)
        s += g_partial[cig][b][h][p][which * 8 + k];
    out[e] = s;
}

extern "C" void kernel_launch(void* const* d_in, const int* in_sizes, int n_in,
                              void* d_out, int out_size) {
    const float* X = (const float*)d_in[0];
    const float* W = (const float*)d_in[1];
    const int* idx = (const int*)d_in[2];
    float* out = (float*)d_out;

    tile_all<<<18 * NTILE * HH * BB, NTHREADS>>>(X, W, idx);
    residue_all<<<15872, NTHREADS>>>(X, W, idx);
    reduce_kernel<<<(BB * 14336 + 255) / 256, 256>>>(out);
}

// round 8
// speedup vs baseline: 1.1186x; 1.0973x over previous
#include <cuda_runtime.h>

#define BB 4
#define CC 17
#define TT 75000
#define HH 32
#define NTHREADS 256
#define TILE 8192
#define NTILE 10          // ceil(75000/8192)
#define MAXPART 32

// Deterministic partial accumulation scratch: [combo 28][b 4][h 32][part 32][16]
__device__ float g_partial[28][4][32][MAXPART][16];

typedef unsigned long long ull;

// ---------------- f32x2 helpers ----------------
__device__ __forceinline__ ull pack2(float a, float b) {
    ull r; asm("mov.b64 %0, {%1, %2};" : "=l"(r) : "f"(a), "f"(b)); return r;
}
__device__ __forceinline__ ull dup2(float a) {
    ull r; asm("mov.b64 %0, {%1, %1};" : "=l"(r) : "f"(a)); return r;
}
__device__ __forceinline__ void mul2(ull& z, ull a, ull b) {
    asm("mul.rn.f32x2 %0, %1, %2;" : "=l"(z) : "l"(a), "l"(b));
}
__device__ __forceinline__ void fma2(ull& z, ull a, ull b) {
    asm("fma.rn.f32x2 %0, %1, %2, %0;" : "+l"(z) : "l"(a), "l"(b));
}
__device__ __forceinline__ void unpack2(ull z, float& lo, float& hi) {
    asm("mov.b64 {%0, %1}, %2;" : "=f"(lo), "=f"(hi) : "l"(z));
}

// ---------------- scalar minmax + bucket ----------------
__device__ __forceinline__ void bucket(const float z[8], float am[8], float an[8],
                                       float vf) {
    float mx = fmaxf(fmaxf(fmaxf(z[0], z[1]), fmaxf(z[2], z[3])),
                     fmaxf(fmaxf(z[4], z[5]), fmaxf(z[6], z[7])));
    float mn = fminf(fminf(fminf(z[0], z[1]), fminf(z[2], z[3])),
                     fminf(fminf(z[4], z[5]), fminf(z[6], z[7])));
#pragma unroll
    for (int k = 0; k < 8; k++) {
        if (z[k] == mx) am[k] += z[k];   // z==0 for invalid pos -> adds 0
        if (z[k] == mn) an[k] += vf;     // masked by validity
    }
}

// k-packed conv step (residue path): gd = 9 dup'd {g,g}, ROT compile-time.
template <int ROT>
__device__ __forceinline__ void conv_step(const ull gd[9], const ull w2[4][9],
                                          float am[8], float an[8]) {
    ull acc[4];
    {
        ull g2 = gd[ROT % 9];
#pragma unroll
        for (int kk = 0; kk < 4; kk++) mul2(acc[kk], g2, w2[kk][0]);
    }
#pragma unroll
    for (int j = 1; j < 9; j++) {
        ull g2 = gd[(ROT + j) % 9];
#pragma unroll
        for (int kk = 0; kk < 4; kk++) fma2(acc[kk], g2, w2[kk][j]);
    }
    float z[8];
#pragma unroll
    for (int kk = 0; kk < 4; kk++) unpack2(acc[kk], z[2 * kk], z[2 * kk + 1]);
    bucket(z, am, an, 1.0f);
}

__device__ __forceinline__ void load_w2(const float* __restrict__ W, int ci, int h,
                                        ull w2[4][9]) {
    const float* wp = W + (ci * 256 + h * 8) * 9;
#pragma unroll
    for (int kk = 0; kk < 4; kk++)
#pragma unroll
        for (int j = 0; j < 9; j++)
            w2[kk][j] = pack2(__ldg(wp + (2 * kk) * 9 + j), __ldg(wp + (2 * kk + 1) * 9 + j));
}

__device__ __forceinline__ void block_write_partial(float* sw, float am[8], float an[8],
                                                    int ci, int b, int h, int blk) {
    int tid = threadIdx.x;
    int lane = tid & 31, warp = tid >> 5;
#pragma unroll
    for (int o = 0; o < 16; o++) {
        float v = (o < 8) ? am[o] : an[o - 8];
        v += __shfl_down_sync(0xffffffffu, v, 16);
        v += __shfl_down_sync(0xffffffffu, v, 8);
        v += __shfl_down_sync(0xffffffffu, v, 4);
        v += __shfl_down_sync(0xffffffffu, v, 2);
        v += __shfl_down_sync(0xffffffffu, v, 1);
        if (lane == 0) sw[warp * 16 + o] = v;
    }
    __syncthreads();
    if (tid < 16) {
        float s = 0.f;
#pragma unroll
        for (int wN = 0; wN < 8; wN++) s += sw[wN * 16 + tid];
        g_partial[ci][b][h][blk][tid] = s;
    }
}

// ============================================================================
// Position-paired conv: positions (t, t+1). LDS.64 {g_t,g_u} feeds FFMA2
// against k-paired weights; acc_a = (zt even-k, zu odd-k), acc_b via swapped
// operand covers the complement.
// ============================================================================
template <int DI>
__device__ __forceinline__ void pair_conv(const float* __restrict__ g_sh, int q,
                                          const ull w2[4][9],
                                          float am[8], float an[8],
                                          float vft, float vfu) {
    constexpr int D = 1 << DI;
    const ull* gp = (const ull*)g_sh;
    ull acc_a[4], acc_b[4];

    if (DI == 0) {
        // window g[q .. q+9]; aligned pairs P[i] = {g[q+2i], g[q+2i+1]}
        ull P[5];
#pragma unroll
        for (int i = 0; i < 5; i++) P[i] = gp[(q >> 1) + i];
        float lo[5], hi[5];
#pragma unroll
        for (int i = 0; i < 5; i++) unpack2(P[i], lo[i], hi[i]);
#pragma unroll
        for (int j = 0; j < 9; j++) {
            ull v, vs;
            if ((j & 1) == 0) {
                v = P[j >> 1];
                vs = pack2(hi[j >> 1], lo[j >> 1]);
            } else {
                v = pack2(hi[(j - 1) >> 1], lo[(j + 1) >> 1]);
                vs = pack2(lo[(j + 1) >> 1], hi[(j - 1) >> 1]);
            }
            if (j == 0) {
#pragma unroll
                for (int kk = 0; kk < 4; kk++) { mul2(acc_a[kk], v, w2[kk][0]); mul2(acc_b[kk], vs, w2[kk][0]); }
            } else {
#pragma unroll
                for (int kk = 0; kk < 4; kk++) { fma2(acc_a[kk], v, w2[kk][j]); fma2(acc_b[kk], vs, w2[kk][j]); }
            }
        }
    } else {
#pragma unroll
        for (int j = 0; j < 9; j++) {
            ull v = gp[(q + j * D) >> 1];    // q even, j*D even -> aligned
            float a, b; unpack2(v, a, b);
            ull vs = pack2(b, a);
            if (j == 0) {
#pragma unroll
                for (int kk = 0; kk < 4; kk++) { mul2(acc_a[kk], v, w2[kk][0]); mul2(acc_b[kk], vs, w2[kk][0]); }
            } else {
#pragma unroll
                for (int kk = 0; kk < 4; kk++) { fma2(acc_a[kk], v, w2[kk][j]); fma2(acc_b[kk], vs, w2[kk][j]); }
            }
        }
    }

    float zt[8], zu[8];
#pragma unroll
    for (int kk = 0; kk < 4; kk++) {
        float al, ah, bl, bh;
        unpack2(acc_a[kk], al, ah);
        unpack2(acc_b[kk], bl, bh);
        zt[2 * kk] = al; zt[2 * kk + 1] = bh;
        zu[2 * kk] = bl; zu[2 * kk + 1] = ah;
    }
    bucket(zt, am, an, vft);
    bucket(zu, am, an, vfu);
}

// ============================================================================
// Path A: small dilation (di 0..8). Scalar g tile + position-paired conv.
// ============================================================================
template <int DI, int DIFF>
__device__ __forceinline__ void tile_body(int rlin, float* g_sh, float* sw,
                                          const float* __restrict__ X,
                                          const float* __restrict__ W,
                                          const int* __restrict__ idx) {
    constexpr int D = 1 << DI;
    constexpr int HALO = 4 * D;
    constexpr int N = TILE + 2 * HALO;
    constexpr int CI = DI * 2 + DIFF;
    constexpr int Te = TT - DIFF;

    int tile = rlin % NTILE;
    int h = (rlin / NTILE) % HH;
    int b = rlin / (NTILE * HH);
    int t0 = tile * TILE;
    int tid = threadIdx.x;

    int off[8];
    {
        const int* ip = idx + (CI * HH + h) * 8;
#pragma unroll
        for (int i = 0; i < 8; i++) off[i] = ip[i] * TT;
    }
    const float* Xb = X + b * CC * TT;

    // ---- build g tile (zero padded outside [0, Te)) ----
    if (DIFF == 0) {
        for (int i = 2 * tid; i < N; i += 2 * NTHREADS) {
            int t = t0 - HALO + i;
            float v0 = 0.f, v1 = 0.f;
            if (t >= 0 && t + 1 < TT) {
#pragma unroll
                for (int c = 0; c < 8; c++) {
                    float2 x = __ldg((const float2*)(Xb + off[c] + t));
                    v0 += x.x; v1 += x.y;
                }
            } else {
                if (t >= 0 && t < TT) {
#pragma unroll
                    for (int c = 0; c < 8; c++) v0 += __ldg(Xb + off[c] + t);
                }
                if (t + 1 >= 0 && t + 1 < TT) {
#pragma unroll
                    for (int c = 0; c < 8; c++) v1 += __ldg(Xb + off[c] + t + 1);
                }
            }
            g_sh[i] = v0;
            g_sh[i + 1] = v1;
        }
    } else {
        for (int i = 2 * tid; i < N; i += 2 * NTHREADS) {
            int t = t0 - HALO + i;
            float s0 = 0.f, s1 = 0.f, s2 = 0.f;
            if (t >= 0 && t + 2 < TT) {
#pragma unroll
                for (int c = 0; c < 8; c++) {
                    float2 x = __ldg((const float2*)(Xb + off[c] + t));
                    s0 += x.x; s1 += x.y;
                    s2 += __ldg(Xb + off[c] + t + 2);
                }
            } else {
                if (t >= 0 && t < TT) {
#pragma unroll
                    for (int c = 0; c < 8; c++) s0 += __ldg(Xb + off[c] + t);
                }
                if (t + 1 >= 0 && t + 1 < TT) {
#pragma unroll
                    for (int c = 0; c < 8; c++) s1 += __ldg(Xb + off[c] + t + 1);
                }
                if (t + 2 >= 0 && t + 2 < TT) {
#pragma unroll
                    for (int c = 0; c < 8; c++) s2 += __ldg(Xb + off[c] + t + 2);
                }
            }
            g_sh[i] = (t >= 0 && t < Te) ? (s1 - s0) : 0.f;
            g_sh[i + 1] = (t + 1 >= 0 && t + 1 < Te) ? (s2 - s1) : 0.f;
        }
    }

    ull w2[4][9];
    load_w2(W, CI, h, w2);
    __syncthreads();

    float am[8] = {0, 0, 0, 0, 0, 0, 0, 0};
    float an[8] = {0, 0, 0, 0, 0, 0, 0, 0};

#pragma unroll 1
    for (int p = 0; p < TILE / (2 * NTHREADS); p++) {
        int q = 2 * tid + p * (2 * NTHREADS);
        int t = t0 + q;
        if (t < Te) {
            float vft = 1.0f;
            float vfu = (t + 1 < Te) ? 1.0f : 0.0f;
            pair_conv<DI>(g_sh, q, w2, am, an, vft, vfu);
        }
    }
    __syncthreads();
    block_write_partial(sw, am, an, CI, b, h, tile);
}

__global__ void __launch_bounds__(256, 2)
tile_all(const float* __restrict__ X, const float* __restrict__ W,
         const int* __restrict__ idx) {
    __shared__ float g_sh[TILE + 2 * 4 * 256];   // max N (DI=8): 10240 floats = 40KB
    __shared__ float sw[128];
    int ci = blockIdx.x / (NTILE * HH * BB);
    int r = blockIdx.x % (NTILE * HH * BB);
    switch (ci) {
        case 0:  tile_body<0, 0>(r, g_sh, sw, X, W, idx); break;
        case 1:  tile_body<0, 1>(r, g_sh, sw, X, W, idx); break;
        case 2:  tile_body<1, 0>(r, g_sh, sw, X, W, idx); break;
        case 3:  tile_body<1, 1>(r, g_sh, sw, X, W, idx); break;
        case 4:  tile_body<2, 0>(r, g_sh, sw, X, W, idx); break;
        case 5:  tile_body<2, 1>(r, g_sh, sw, X, W, idx); break;
        case 6:  tile_body<3, 0>(r, g_sh, sw, X, W, idx); break;
        case 7:  tile_body<3, 1>(r, g_sh, sw, X, W, idx); break;
        case 8:  tile_body<4, 0>(r, g_sh, sw, X, W, idx); break;
        case 9:  tile_body<4, 1>(r, g_sh, sw, X, W, idx); break;
        case 10: tile_body<5, 0>(r, g_sh, sw, X, W, idx); break;
        case 11: tile_body<5, 1>(r, g_sh, sw, X, W, idx); break;
        case 12: tile_body<6, 0>(r, g_sh, sw, X, W, idx); break;
        case 13: tile_body<6, 1>(r, g_sh, sw, X, W, idx); break;
        case 14: tile_body<7, 0>(r, g_sh, sw, X, W, idx); break;
        case 15: tile_body<7, 1>(r, g_sh, sw, X, W, idx); break;
        case 16: tile_body<8, 0>(r, g_sh, sw, X, W, idx); break;
        case 17: tile_body<8, 1>(r, g_sh, sw, X, W, idx); break;
    }
}

// ============================================================================
// Path B: large dilation (di 9..13). Residue walk, CLEAN rotation window
// (1 dup2 per slide, no shift MOVs, no dead code).
// ============================================================================
template <int DIFF>
__device__ __forceinline__ float gsumT(const float* __restrict__ Xb,
                                       const int off[8], int t) {
    float s = 0.f;
#pragma unroll
    for (int i = 0; i < 8; i++) {
        const float* p = Xb + off[i] + t;
        float x = __ldg(p);
        if (DIFF) x = __ldg(p + 1) - x;
        s += x;
    }
    return s;
}

template <int DI, int DIFF, int U>
__device__ __forceinline__ void residue_step(ull gd[9], const ull w2[4][9],
                                             float am[8], float an[8],
                                             const float* __restrict__ Xb,
                                             const int off[8], int r, int mb, int M) {
    constexpr int D = 1 << DI;
    int m = mb + U;
    if (m < M) {
        conv_step<U>(gd, w2, am, an);
        int sn = m + 5;
        gd[U] = dup2((sn < M) ? gsumT<DIFF>(Xb, off, r + sn * D) : 0.f);
    }
}

template <int DI, int DIFF>
__device__ __forceinline__ void residue_body(int rlin, float* sw,
                                             const float* __restrict__ X,
                                             const float* __restrict__ W,
                                             const int* __restrict__ idx) {
    constexpr int D = 1 << DI;
    constexpr int NRB = 1 << (DI - 8);
    constexpr int CI = 18 + (DI - 9) * 2 + DIFF;
    constexpr int Te = TT - DIFF;

    int rb = rlin % NRB;
    int h = (rlin / NRB) % HH;
    int b = rlin / (NRB * HH);
    int tid = threadIdx.x;
    int r = rb * NTHREADS + tid;            // residue < D
    int M = (Te - r + D - 1) / D;           // strip length >= 1

    int off[8];
    {
        const int* ip = idx + (CI * HH + h) * 8;
#pragma unroll
        for (int i = 0; i < 8; i++) off[i] = ip[i] * TT;
    }
    const float* Xb = X + b * CC * TT;

    ull w2[4][9];
    load_w2(W, CI, h, w2);

    ull gd[9];
#pragma unroll
    for (int j = 0; j < 9; j++) {
        int s = j - 4;
        gd[j] = dup2((s >= 0 && s < M) ? gsumT<DIFF>(Xb, off, r + s * D) : 0.f);
    }

    float am[8] = {0, 0, 0, 0, 0, 0, 0, 0};
    float an[8] = {0, 0, 0, 0, 0, 0, 0, 0};

#pragma unroll 1
    for (int mb = 0; mb < M; mb += 9) {
        residue_step<DI, DIFF, 0>(gd, w2, am, an, Xb, off, r, mb, M);
        residue_step<DI, DIFF, 1>(gd, w2, am, an, Xb, off, r, mb, M);
        residue_step<DI, DIFF, 2>(gd, w2, am, an, Xb, off, r, mb, M);
        residue_step<DI, DIFF, 3>(gd, w2, am, an, Xb, off, r, mb, M);
        residue_step<DI, DIFF, 4>(gd, w2, am, an, Xb, off, r, mb, M);
        residue_step<DI, DIFF, 5>(gd, w2, am, an, Xb, off, r, mb, M);
        residue_step<DI, DIFF, 6>(gd, w2, am, an, Xb, off, r, mb, M);
        residue_step<DI, DIFF, 7>(gd, w2, am, an, Xb, off, r, mb, M);
        residue_step<DI, DIFF, 8>(gd, w2, am, an, Xb, off, r, mb, M);
    }
    __syncthreads();
    block_write_partial(sw, am, an, CI, b, h, rb);
}

__global__ void __launch_bounds__(256, 2)
residue_all(const float* __restrict__ X, const float* __restrict__ W,
            const int* __restrict__ idx) {
    __shared__ float sw[128];
    int bx = blockIdx.x;
    int lci, r;
    if      (bx < 256)   { lci = 0; r = bx; }
    else if (bx < 512)   { lci = 1; r = bx - 256; }
    else if (bx < 1024)  { lci = 2; r = bx - 512; }
    else if (bx < 1536)  { lci = 3; r = bx - 1024; }
    else if (bx < 2560)  { lci = 4; r = bx - 1536; }
    else if (bx < 3584)  { lci = 5; r = bx - 2560; }
    else if (bx < 5632)  { lci = 6; r = bx - 3584; }
    else if (bx < 7680)  { lci = 7; r = bx - 5632; }
    else if (bx < 11776) { lci = 8; r = bx - 7680; }
    else                 { lci = 9; r = bx - 11776; }
    switch (lci) {
        case 0: residue_body<9, 0>(r, sw, X, W, idx); break;
        case 1: residue_body<9, 1>(r, sw, X, W, idx); break;
        case 2: residue_body<10, 0>(r, sw, X, W, idx); break;
        case 3: residue_body<10, 1>(r, sw, X, W, idx); break;
        case 4: residue_body<11, 0>(r, sw, X, W, idx); break;
        case 5: residue_body<11, 1>(r, sw, X, W, idx); break;
        case 6: residue_body<12, 0>(r, sw, X, W, idx); break;
        case 7: residue_body<12, 1>(r, sw, X, W, idx); break;
        case 8: residue_body<13, 0>(r, sw, X, W, idx); break;
        case 9: residue_body<13, 1>(r, sw, X, W, idx); break;
    }
}

// ============================================================================
// Deterministic final reduction -> d_out (writes every element)
// ============================================================================
__global__ void reduce_kernel(float* __restrict__ out) {
    int e = blockIdx.x * 256 + threadIdx.x;
    if (e >= BB * 14336) return;
    int b = e / 14336;
    int rem = e % 14336;
    int cig = rem / 512;
    int r2 = rem % 512;
    int which = r2 / 256;
    int hk = r2 % 256;
    int h = hk >> 3, k = hk & 7;
    int np;
    if (cig < 18) np = NTILE;
    else { int di = cig >> 1; np = 1 << (di - 8); }
    float s = 0.f;
    for (int p = 0; p < np; p++)
        s += g_partial[cig][b][h][p][which * 8 + k];
    out[e] = s;
}

extern "C" void kernel_launch(void* const* d_in, const int* in_sizes, int n_in,
                              void* d_out, int out_size) {
    const float* X = (const float*)d_in[0];
    const float* W = (const float*)d_in[1];
    const int* idx = (const int*)d_in[2];
    float* out = (float*)d_out;

    tile_all<<<18 * NTILE * HH * BB, NTHREADS>>>(X, W, idx);
    residue_all<<<15872, NTHREADS>>>(X, W, idx);
    reduce_kernel<<<(BB * 14336 + 255) / 256, 256>>>(out);
}

// round 9
// speedup vs baseline: 1.1647x; 1.0412x over previous
#include <cuda_runtime.h>

#define BB 4
#define CC 17
#define TT 75000
#define HH 32
#define NTHREADS 256
#define TILE 8192
#define NTILE 10          // ceil(75000/8192)
#define MAXPART 256

// Deterministic partial accumulation scratch: [combo 28][b 4][h 32][part 256][16]
__device__ float g_partial[28][4][32][MAXPART][16];

typedef unsigned long long ull;

// ---------------- f32x2 helpers ----------------
__device__ __forceinline__ ull pack2(float a, float b) {
    ull r; asm("mov.b64 %0, {%1, %2};" : "=l"(r) : "f"(a), "f"(b)); return r;
}
__device__ __forceinline__ ull dup2(float a) {
    ull r; asm("mov.b64 %0, {%1, %1};" : "=l"(r) : "f"(a)); return r;
}
__device__ __forceinline__ void mul2(ull& z, ull a, ull b) {
    asm("mul.rn.f32x2 %0, %1, %2;" : "=l"(z) : "l"(a), "l"(b));
}
__device__ __forceinline__ void fma2(ull& z, ull a, ull b) {
    asm("fma.rn.f32x2 %0, %1, %2, %0;" : "+l"(z) : "l"(a), "l"(b));
}
__device__ __forceinline__ void unpack2(ull z, float& lo, float& hi) {
    asm("mov.b64 {%0, %1}, %2;" : "=f"(lo), "=f"(hi) : "l"(z));
}

// ---------------- scalar minmax + bucket ----------------
__device__ __forceinline__ void bucket(const float z[8], float am[8], float an[8],
                                       float vf) {
    float mx = fmaxf(fmaxf(fmaxf(z[0], z[1]), fmaxf(z[2], z[3])),
                     fmaxf(fmaxf(z[4], z[5]), fmaxf(z[6], z[7])));
    float mn = fminf(fminf(fminf(z[0], z[1]), fminf(z[2], z[3])),
                     fminf(fminf(z[4], z[5]), fminf(z[6], z[7])));
#pragma unroll
    for (int k = 0; k < 8; k++) {
        if (z[k] == mx) am[k] += z[k];   // z==0 for invalid pos -> adds 0
        if (z[k] == mn) an[k] += vf;     // masked by validity
    }
}

// k-packed conv step (residue path): gd = 9 dup'd {g,g}, ROT compile-time.
// w2[kk][j] = { w[2kk][j], w[2kk+1][j] }
template <int ROT>
__device__ __forceinline__ void conv_step(const ull gd[9], const ull w2[4][9],
                                          float am[8], float an[8]) {
    ull acc[4];
    {
        ull g2 = gd[ROT % 9];
#pragma unroll
        for (int kk = 0; kk < 4; kk++) mul2(acc[kk], g2, w2[kk][0]);
    }
#pragma unroll
    for (int j = 1; j < 9; j++) {
        ull g2 = gd[(ROT + j) % 9];
#pragma unroll
        for (int kk = 0; kk < 4; kk++) fma2(acc[kk], g2, w2[kk][j]);
    }
    float z[8];
#pragma unroll
    for (int kk = 0; kk < 4; kk++) unpack2(acc[kk], z[2 * kk], z[2 * kk + 1]);
    bucket(z, am, an, 1.0f);
}

// residue-path weights: k-paired
__device__ __forceinline__ void load_w2(const float* __restrict__ W, int ci, int h,
                                        ull w2[4][9]) {
    const float* wp = W + (ci * 256 + h * 8) * 9;
#pragma unroll
    for (int kk = 0; kk < 4; kk++)
#pragma unroll
        for (int j = 0; j < 9; j++)
            w2[kk][j] = pack2(__ldg(wp + (2 * kk) * 9 + j), __ldg(wp + (2 * kk + 1) * 9 + j));
}

// tile-path weights: duplicated {w,w} (positions in SIMD lanes)
__device__ __forceinline__ void load_wd(const float* __restrict__ W, int ci, int h,
                                        ull wd[8][9]) {
    const float* wp = W + (ci * 256 + h * 8) * 9;
#pragma unroll
    for (int k = 0; k < 8; k++)
#pragma unroll
        for (int j = 0; j < 9; j++)
            wd[k][j] = dup2(__ldg(wp + k * 9 + j));
}

__device__ __forceinline__ void block_write_partial(float* sw, float am[8], float an[8],
                                                    int ci, int b, int h, int blk) {
    int tid = threadIdx.x;
    int lane = tid & 31, warp = tid >> 5;
#pragma unroll
    for (int o = 0; o < 16; o++) {
        float v = (o < 8) ? am[o] : an[o - 8];
        v += __shfl_down_sync(0xffffffffu, v, 16);
        v += __shfl_down_sync(0xffffffffu, v, 8);
        v += __shfl_down_sync(0xffffffffu, v, 4);
        v += __shfl_down_sync(0xffffffffu, v, 2);
        v += __shfl_down_sync(0xffffffffu, v, 1);
        if (lane == 0) sw[warp * 16 + o] = v;
    }
    __syncthreads();
    if (tid < 16) {
        float s = 0.f;
#pragma unroll
        for (int wN = 0; wN < 8; wN++) s += sw[wN * 16 + tid];
        g_partial[ci][b][h][blk][tid] = s;
    }
}

// per-warp partial write (residue path, one h per warp)
__device__ __forceinline__ void warp_write_partial(float am[8], float an[8],
                                                   int ci, int b, int h, int part) {
    int lane = threadIdx.x & 31;
#pragma unroll
    for (int o = 0; o < 16; o++) {
        float v = (o < 8) ? am[o] : an[o - 8];
        v += __shfl_down_sync(0xffffffffu, v, 16);
        v += __shfl_down_sync(0xffffffffu, v, 8);
        v += __shfl_down_sync(0xffffffffu, v, 4);
        v += __shfl_down_sync(0xffffffffu, v, 2);
        v += __shfl_down_sync(0xffffffffu, v, 1);
        if (lane == 0) g_partial[ci][b][h][part][o] = v;
    }
}

// ============================================================================
// Position-paired conv, dup'd weights: one aligned LDS.64 {g_t+jD, g_t+jD+1}
// feeds all 8 k-accumulators; acc[k] = {z_t[k], z_u[k]}. No swap MOVs.
// ============================================================================
template <int DI>
__device__ __forceinline__ void pair_conv(const float* __restrict__ g_sh, int q,
                                          const ull wd[8][9],
                                          float am[8], float an[8],
                                          float vft, float vfu) {
    constexpr int D = 1 << DI;
    const ull* gp = (const ull*)g_sh;
    ull acc[8];

    if (DI == 0) {
        // window g[q .. q+9]; aligned pairs P[i] = {g[q+2i], g[q+2i+1]}
        ull P[5];
#pragma unroll
        for (int i = 0; i < 5; i++) P[i] = gp[(q >> 1) + i];
        float lo[5], hi[5];
#pragma unroll
        for (int i = 0; i < 5; i++) unpack2(P[i], lo[i], hi[i]);
#pragma unroll
        for (int j = 0; j < 9; j++) {
            ull v = ((j & 1) == 0) ? P[j >> 1]
                                   : pack2(hi[(j - 1) >> 1], lo[(j + 1) >> 1]);
            if (j == 0) {
#pragma unroll
                for (int k = 0; k < 8; k++) mul2(acc[k], v, wd[k][0]);
            } else {
#pragma unroll
                for (int k = 0; k < 8; k++) fma2(acc[k], v, wd[k][j]);
            }
        }
    } else {
#pragma unroll
        for (int j = 0; j < 9; j++) {
            ull v = gp[(q + j * D) >> 1];    // q even, j*D even -> aligned LDS.64
            if (j == 0) {
#pragma unroll
                for (int k = 0; k < 8; k++) mul2(acc[k], v, wd[k][0]);
            } else {
#pragma unroll
                for (int k = 0; k < 8; k++) fma2(acc[k], v, wd[k][j]);
            }
        }
    }

    float zt[8], zu[8];
#pragma unroll
    for (int k = 0; k < 8; k++) unpack2(acc[k], zt[k], zu[k]);
    bucket(zt, am, an, vft);
    bucket(zu, am, an, vfu);
}

// ============================================================================
// Path A: small dilation (di 0..8). Scalar g tile + position-paired conv.
// ============================================================================
template <int DI, int DIFF>
__device__ __forceinline__ void tile_body(int rlin, float* g_sh, float* sw,
                                          const float* __restrict__ X,
                                          const float* __restrict__ W,
                                          const int* __restrict__ idx) {
    constexpr int D = 1 << DI;
    constexpr int HALO = 4 * D;
    constexpr int N = TILE + 2 * HALO;
    constexpr int CI = DI * 2 + DIFF;
    constexpr int Te = TT - DIFF;

    int tile = rlin % NTILE;
    int h = (rlin / NTILE) % HH;
    int b = rlin / (NTILE * HH);
    int t0 = tile * TILE;
    int tid = threadIdx.x;

    int off[8];
    {
        const int* ip = idx + (CI * HH + h) * 8;
#pragma unroll
        for (int i = 0; i < 8; i++) off[i] = ip[i] * TT;
    }
    const float* Xb = X + b * CC * TT;

    // ---- build g tile (zero padded outside [0, Te)) ----
    if (DIFF == 0) {
        for (int i = 2 * tid; i < N; i += 2 * NTHREADS) {
            int t = t0 - HALO + i;
            float v0 = 0.f, v1 = 0.f;
            if (t >= 0 && t + 1 < TT) {
#pragma unroll
                for (int c = 0; c < 8; c++) {
                    float2 x = __ldg((const float2*)(Xb + off[c] + t));
                    v0 += x.x; v1 += x.y;
                }
            } else {
                if (t >= 0 && t < TT) {
#pragma unroll
                    for (int c = 0; c < 8; c++) v0 += __ldg(Xb + off[c] + t);
                }
                if (t + 1 >= 0 && t + 1 < TT) {
#pragma unroll
                    for (int c = 0; c < 8; c++) v1 += __ldg(Xb + off[c] + t + 1);
                }
            }
            g_sh[i] = v0;
            g_sh[i + 1] = v1;
        }
    } else {
        for (int i = 2 * tid; i < N; i += 2 * NTHREADS) {
            int t = t0 - HALO + i;
            float s0 = 0.f, s1 = 0.f, s2 = 0.f;
            if (t >= 0 && t + 2 < TT) {
#pragma unroll
                for (int c = 0; c < 8; c++) {
                    float2 x = __ldg((const float2*)(Xb + off[c] + t));
                    s0 += x.x; s1 += x.y;
                    s2 += __ldg(Xb + off[c] + t + 2);
                }
            } else {
                if (t >= 0 && t < TT) {
#pragma unroll
                    for (int c = 0; c < 8; c++) s0 += __ldg(Xb + off[c] + t);
                }
                if (t + 1 >= 0 && t + 1 < TT) {
#pragma unroll
                    for (int c = 0; c < 8; c++) s1 += __ldg(Xb + off[c] + t + 1);
                }
                if (t + 2 >= 0 && t + 2 < TT) {
#pragma unroll
                    for (int c = 0; c < 8; c++) s2 += __ldg(Xb + off[c] + t + 2);
                }
            }
            g_sh[i] = (t >= 0 && t < Te) ? (s1 - s0) : 0.f;
            g_sh[i + 1] = (t + 1 >= 0 && t + 1 < Te) ? (s2 - s1) : 0.f;
        }
    }

    ull wd[8][9];
    load_wd(W, CI, h, wd);
    __syncthreads();

    float am[8] = {0, 0, 0, 0, 0, 0, 0, 0};
    float an[8] = {0, 0, 0, 0, 0, 0, 0, 0};

#pragma unroll 1
    for (int p = 0; p < TILE / (2 * NTHREADS); p++) {
        int q = 2 * tid + p * (2 * NTHREADS);
        int t = t0 + q;
        if (t < Te) {
            float vft = 1.0f;
            float vfu = (t + 1 < Te) ? 1.0f : 0.0f;
            pair_conv<DI>(g_sh, q, wd, am, an, vft, vfu);
        }
    }
    __syncthreads();
    block_write_partial(sw, am, an, CI, b, h, tile);
}

__global__ void __launch_bounds__(256, 2)
tile_all(const float* __restrict__ X, const float* __restrict__ W,
         const int* __restrict__ idx) {
    __shared__ float g_sh[TILE + 2 * 4 * 256];   // max N (DI=8): 10240 floats = 40KB
    __shared__ float sw[128];
    int ci = blockIdx.x / (NTILE * HH * BB);
    int r = blockIdx.x % (NTILE * HH * BB);
    switch (ci) {
        case 0:  tile_body<0, 0>(r, g_sh, sw, X, W, idx); break;
        case 1:  tile_body<0, 1>(r, g_sh, sw, X, W, idx); break;
        case 2:  tile_body<1, 0>(r, g_sh, sw, X, W, idx); break;
        case 3:  tile_body<1, 1>(r, g_sh, sw, X, W, idx); break;
        case 4:  tile_body<2, 0>(r, g_sh, sw, X, W, idx); break;
        case 5:  tile_body<2, 1>(r, g_sh, sw, X, W, idx); break;
        case 6:  tile_body<3, 0>(r, g_sh, sw, X, W, idx); break;
        case 7:  tile_body<3, 1>(r, g_sh, sw, X, W, idx); break;
        case 8:  tile_body<4, 0>(r, g_sh, sw, X, W, idx); break;
        case 9:  tile_body<4, 1>(r, g_sh, sw, X, W, idx); break;
        case 10: tile_body<5, 0>(r, g_sh, sw, X, W, idx); break;
        case 11: tile_body<5, 1>(r, g_sh, sw, X, W, idx); break;
        case 12: tile_body<6, 0>(r, g_sh, sw, X, W, idx); break;
        case 13: tile_body<6, 1>(r, g_sh, sw, X, W, idx); break;
        case 14: tile_body<7, 0>(r, g_sh, sw, X, W, idx); break;
        case 15: tile_body<7, 1>(r, g_sh, sw, X, W, idx); break;
        case 16: tile_body<8, 0>(r, g_sh, sw, X, W, idx); break;
        case 17: tile_body<8, 1>(r, g_sh, sw, X, W, idx); break;
    }
}

// ============================================================================
// Path B: large dilation (di 9..13). Residue walk, rotation window,
// h-GROUPED: 8 warps = 8 h per block share the same (b, 32-residue window)
// so X lines hit L1 instead of being re-fetched from L2 per h.
// ============================================================================
template <int DIFF>
__device__ __forceinline__ float gsumT(const float* __restrict__ Xb,
                                       const int off[8], int t) {
    float s = 0.f;
#pragma unroll
    for (int i = 0; i < 8; i++) {
        const float* p = Xb + off[i] + t;
        float x = __ldg(p);
        if (DIFF) x = __ldg(p + 1) - x;
        s += x;
    }
    return s;
}

template <int DI, int DIFF, int U>
__device__ __forceinline__ void residue_step(ull gd[9], const ull w2[4][9],
                                             float am[8], float an[8],
                                             const float* __restrict__ Xb,
                                             const int off[8], int r, int mb, int M) {
    constexpr int D = 1 << DI;
    int m = mb + U;
    if (m < M) {
        conv_step<U>(gd, w2, am, an);
        int sn = m + 5;
        gd[U] = dup2((sn < M) ? gsumT<DIFF>(Xb, off, r + sn * D) : 0.f);
    }
}

template <int DI, int DIFF>
__device__ __forceinline__ void residue_body(int rlin,
                                             const float* __restrict__ X,
                                             const float* __restrict__ W,
                                             const int* __restrict__ idx) {
    constexpr int D = 1 << DI;
    constexpr int NRB32 = 1 << (DI - 5);    // 32-residue windows
    constexpr int CI = 18 + (DI - 9) * 2 + DIFF;
    constexpr int Te = TT - DIFF;

    int rb = rlin % NRB32;
    int hb = (rlin / NRB32) & 3;
    int b = rlin / (NRB32 * 4);
    int lane = threadIdx.x & 31;
    int warp = threadIdx.x >> 5;
    int h = hb * 8 + warp;
    int r = rb * 32 + lane;                 // residue < D
    int M = (Te - r + D - 1) / D;           // strip length >= 1

    int off[8];
    {
        const int* ip = idx + (CI * HH + h) * 8;
#pragma unroll
        for (int i = 0; i < 8; i++) off[i] = ip[i] * TT;
    }
    const float* Xb = X + b * CC * TT;

    ull w2[4][9];
    load_w2(W, CI, h, w2);

    ull gd[9];
#pragma unroll
    for (int j = 0; j < 9; j++) {
        int s = j - 4;
        gd[j] = dup2((s >= 0 && s < M) ? gsumT<DIFF>(Xb, off, r + s * D) : 0.f);
    }

    float am[8] = {0, 0, 0, 0, 0, 0, 0, 0};
    float an[8] = {0, 0, 0, 0, 0, 0, 0, 0};

#pragma unroll 1
    for (int mb = 0; mb < M; mb += 9) {
        residue_step<DI, DIFF, 0>(gd, w2, am, an, Xb, off, r, mb, M);
        residue_step<DI, DIFF, 1>(gd, w2, am, an, Xb, off, r, mb, M);
        residue_step<DI, DIFF, 2>(gd, w2, am, an, Xb, off, r, mb, M);
        residue_step<DI, DIFF, 3>(gd, w2, am, an, Xb, off, r, mb, M);
        residue_step<DI, DIFF, 4>(gd, w2, am, an, Xb, off, r, mb, M);
        residue_step<DI, DIFF, 5>(gd, w2, am, an, Xb, off, r, mb, M);
        residue_step<DI, DIFF, 6>(gd, w2, am, an, Xb, off, r, mb, M);
        residue_step<DI, DIFF, 7>(gd, w2, am, an, Xb, off, r, mb, M);
        residue_step<DI, DIFF, 8>(gd, w2, am, an, Xb, off, r, mb, M);
    }
    warp_write_partial(am, an, CI, b, h, rb);
}

__global__ void __launch_bounds__(256, 2)
residue_all(const float* __restrict__ X, const float* __restrict__ W,
            const int* __restrict__ idx) {
    int bx = blockIdx.x;
    int lci, r;
    if      (bx < 256)   { lci = 0; r = bx; }
    else if (bx < 512)   { lci = 1; r = bx - 256; }
    else if (bx < 1024)  { lci = 2; r = bx - 512; }
    else if (bx < 1536)  { lci = 3; r = bx - 1024; }
    else if (bx < 2560)  { lci = 4; r = bx - 1536; }
    else if (bx < 3584)  { lci = 5; r = bx - 2560; }
    else if (bx < 5632)  { lci = 6; r = bx - 3584; }
    else if (bx < 7680)  { lci = 7; r = bx - 5632; }
    else if (bx < 11776) { lci = 8; r = bx - 7680; }
    else                 { lci = 9; r = bx - 11776; }
    switch (lci) {
        case 0: residue_body<9, 0>(r, X, W, idx); break;
        case 1: residue_body<9, 1>(r, X, W, idx); break;
        case 2: residue_body<10, 0>(r, X, W, idx); break;
        case 3: residue_body<10, 1>(r, X, W, idx); break;
        case 4: residue_body<11, 0>(r, X, W, idx); break;
        case 5: residue_body<11, 1>(r, X, W, idx); break;
        case 6: residue_body<12, 0>(r, X, W, idx); break;
        case 7: residue_body<12, 1>(r, X, W, idx); break;
        case 8: residue_body<13, 0>(r, X, W, idx); break;
        case 9: residue_body<13, 1>(r, X, W, idx); break;
    }
}

// ============================================================================
// Deterministic final reduction -> d_out (writes every element)
// ============================================================================
__global__ void reduce_kernel(float* __restrict__ out) {
    int e = blockIdx.x * 256 + threadIdx.x;
    if (e >= BB * 14336) return;
    int b = e / 14336;
    int rem = e % 14336;
    int cig = rem / 512;
    int r2 = rem % 512;
    int which = r2 / 256;
    int hk = r2 % 256;
    int h = hk >> 3, k = hk & 7;
    int np;
    if (cig < 18) np = NTILE;
    else np = 1 << (((cig - 18) >> 1) + 4);   // D/32 windows
    float s = 0.f;
    for (int p = 0; p < np; p++)
        s += g_partial[cig][b][h][p][which * 8 + k];
    out[e] = s;
}

extern "C" void kernel_launch(void* const* d_in, const int* in_sizes, int n_in,
                              void* d_out, int out_size) {
    const float* X = (const float*)d_in[0];
    const float* W = (const float*)d_in[1];
    const int* idx = (const int*)d_in[2];
    float* out = (float*)d_out;

    tile_all<<<18 * NTILE * HH * BB, NTHREADS>>>(X, W, idx);
    residue_all<<<15872, NTHREADS>>>(X, W, idx);
    reduce_kernel<<<(BB * 14336 + 255) / 256, 256>>>(out);
}